// round 17
// baseline (speedup 1.0000x reference)
#include <cuda_runtime.h>
#include <cuda_fp16.h>
#include <cuda_fp8.h>

#define NN 50000
#define EE 800000
#define D  128
#define G  8
#define C  10

// ---------------- scratch (static device globals; no allocs allowed) --------
__device__ float         g_in_isqrt[NN];
__device__ unsigned char g_h8A[NN * D];
__device__ unsigned char g_h8B[NN * D];
__device__ __half        g_W1h[D * D];
__device__ __half        g_W2h[D * D];
__device__ float         g_sums[G * D];
__device__ int           g_outcnt[NN];
__device__ int           g_incnt[NN];
__device__ int           g_rowptr[NN + 1];
__device__ int           g_cursor[NN];
__device__ int           g_csr[EE];
__device__ int           g_bsums[256];

// ---------------- fp8 helpers ---------------------------------------------------
__device__ __forceinline__ unsigned short pack_fp8x2(float a, float b) {
    float2 f = make_float2(a, b);
    return __nv_cvt_float2_to_fp8x2(f, __NV_SATFINITE, __NV_E4M3);
}
__device__ __forceinline__ float2 unpack_fp8x2(unsigned v) {
    __half2_raw hr = __nv_cvt_fp8x2_to_halfraw2((__nv_fp8x2_storage_t)v, __NV_E4M3);
    return __half22float2(*(__half2*)&hr);
}
__device__ __forceinline__ __half2 fp8x2_to_h2(unsigned v) {
    __half2_raw hr = __nv_cvt_fp8x2_to_halfraw2((__nv_fp8x2_storage_t)v, __NV_E4M3);
    return *(__half2*)&hr;
}

// ---------------- prep (main): zero outc + convert weights ---------------------
__global__ __launch_bounds__(256)
void k_prep(int* __restrict__ outc, int n,
            const float* __restrict__ W1, const float* __restrict__ W2,
            __half* __restrict__ w1h, __half* __restrict__ w2h) {
    int i = blockIdx.x * 256 + threadIdx.x;
    if (i < n) outc[i] = 0;
    if (i < D * D) {
        int k = i >> 7, nn = i & 127;
        w1h[nn * D + k] = __float2half_rn(W1[i]);
        w2h[nn * D + k] = __float2half_rn(W2[i]);
    }
}

// ---------------- zero2 (s1): zero inc + pool sums ------------------------------
__global__ __launch_bounds__(256)
void k_zero2(int* __restrict__ inc, int n, float* __restrict__ sums) {
    int i = blockIdx.x * 256 + threadIdx.x;
    if (i < n) inc[i] = 0;
    if (i < G * D) sums[i] = 0.0f;
}

// ---------------- degree histograms ---------------------------------------------
__global__ void k_degout(const int* __restrict__ ei, int E, int* __restrict__ outc) {
    int e = blockIdx.x * blockDim.x + threadIdx.x;
    if (e < E) atomicAdd(&outc[ei[e]], 1);
}
__global__ void k_degin(const int* __restrict__ ei, int E, int* __restrict__ inc) {
    int e = blockIdx.x * blockDim.x + threadIdx.x;
    if (e < E) atomicAdd(&inc[ei[E + e]], 1);
}

// ---------------- scan helpers -------------------------------------------------
__device__ __forceinline__ int warp_incl_scan(int v, int lane) {
#pragma unroll
    for (int o = 1; o < 32; o <<= 1) {
        int t = __shfl_up_sync(0xffffffffu, v, o);
        if (lane >= o) v += t;
    }
    return v;
}

__device__ __forceinline__ int block_incl_scan(int v, int tid, int* ws) {
    int lane = tid & 31, wid = tid >> 5;
    int s = warp_incl_scan(v, lane);
    if (lane == 31) ws[wid] = s;
    __syncthreads();
    if (wid == 0) {
        int t = (lane < 8) ? ws[lane] : 0;
        t = warp_incl_scan(t, lane);
        if (lane < 8) ws[lane] = t;
    }
    __syncthreads();
    return s + (wid > 0 ? ws[wid - 1] : 0);
}

__global__ __launch_bounds__(256)
void k_scan1(const int* __restrict__ inc, int n, int* __restrict__ bsums) {
    __shared__ int ws[8];
    int tid = threadIdx.x;
    int i = blockIdx.x * 256 + tid;
    int v = (i < n) ? inc[i] : 0;
    int incl = block_incl_scan(v, tid, ws);
    if (tid == 255) bsums[blockIdx.x] = incl;
}

__global__ __launch_bounds__(256)
void k_scan3(const int* __restrict__ inc, int n, int nb, int E,
             const int* __restrict__ bsums, int* __restrict__ rowp,
             int* __restrict__ cur, float* __restrict__ iq) {
    __shared__ int ws[8];
    __shared__ int soff[256];
    int tid = threadIdx.x;

    int vb = (tid < nb) ? bsums[tid] : 0;
    int inclb = block_incl_scan(vb, tid, ws);
    soff[tid] = inclb - vb;
    __syncthreads();
    int blockoff = soff[blockIdx.x];
    __syncthreads();

    int i = blockIdx.x * 256 + tid;
    int v = (i < n) ? inc[i] : 0;
    int incl = block_incl_scan(v, tid, ws);
    if (i < n) {
        int ex = incl - v + blockoff;
        rowp[i] = ex;
        cur[i] = ex;
        iq[i] = rsqrtf((float)max(v, 1));
    }
    if (blockIdx.x == 0 && tid == 0) rowp[n] = E;
}

// ---------------- CSR fill -----------------------------------------------------
__global__ void k_fill(const int* __restrict__ ei, int E,
                       int* __restrict__ cur, int* __restrict__ csr) {
    int e = blockIdx.x * blockDim.x + threadIdx.x;
    if (e < E) {
        int d = ei[E + e];
        int pos = atomicAdd(&cur[d], 1);
        csr[pos] = ei[e];
    }
}

// ---------------- MMA helper ----------------------------------------------------
__device__ __forceinline__ void mma16816(float* c, const unsigned* a,
                                         unsigned b0, unsigned b1) {
    asm volatile(
        "mma.sync.aligned.m16n8k16.row.col.f32.f16.f16.f32 "
        "{%0,%1,%2,%3}, {%4,%5,%6,%7}, {%8,%9}, {%0,%1,%2,%3};"
        : "+f"(c[0]), "+f"(c[1]), "+f"(c[2]), "+f"(c[3])
        : "r"(a[0]), "r"(a[1]), "r"(a[2]), "r"(a[3]), "r"(b0), "r"(b1));
}

#define LDA 136   // padded smem stride in halves

// ---------------- MMA phase for 64-row tile (8 warps: 4 row-groups x 2 col) ----
__device__ __forceinline__ void mma_phase64(
    const __half* As, const __half* Bh,
    unsigned char* __restrict__ Cm, int rowBase, int nrows,
    int wr, int wc, int g, int tg) {
    float acc[8][4];
#pragma unroll
    for (int nt = 0; nt < 8; nt++)
#pragma unroll
        for (int q = 0; q < 4; q++) acc[nt][q] = 0.0f;

#pragma unroll
    for (int ks = 0; ks < 8; ks++) {
        const int k0 = ks * 16;
        unsigned a[4];
        const __half* pr = As + (wr * 16 + g) * LDA + k0 + tg * 2;
        a[0] = *(const unsigned*)(pr);
        a[1] = *(const unsigned*)(pr + 8 * LDA);
        a[2] = *(const unsigned*)(pr + 8);
        a[3] = *(const unsigned*)(pr + 8 * LDA + 8);
#pragma unroll
        for (int nt = 0; nt < 8; nt++) {
            const int n = wc * 64 + nt * 8 + g;
            const __half* ph = Bh + n * LDA + k0 + tg * 2;
            unsigned bh0 = *(const unsigned*)(ph);
            unsigned bh1 = *(const unsigned*)(ph + 8);
            mma16816(acc[nt], a, bh0, bh1);
        }
    }

    int r0 = rowBase + wr * 16 + g;
    int r1 = r0 + 8;
#pragma unroll
    for (int nt = 0; nt < 8; nt++) {
        int col = wc * 64 + nt * 8 + tg * 2;
        if (r0 < nrows)
            *(unsigned short*)(Cm + (size_t)r0 * D + col) =
                pack_fp8x2(acc[nt][0], acc[nt][1]);
        if (r1 < nrows)
            *(unsigned short*)(Cm + (size_t)r1 * D + col) =
                pack_fp8x2(acc[nt][2], acc[nt][3]);
    }
}

// ---------------- layer-1 GEMM: 64-row tile, fp32 A scaled, fp8 out ------------
__global__ __launch_bounds__(256, 4)
void k_gemm_tc(const float* __restrict__ A, const int* __restrict__ outc,
               const __half* __restrict__ Whi,
               unsigned char* __restrict__ Cm, int nrows) {
    extern __shared__ __half sm[];
    __half* As = sm;                    // 64 x LDA
    __half* Bh = sm + 64 * LDA;         // 128 x LDA

    const int tid = threadIdx.x;
    const int wid = tid >> 5, lane = tid & 31;
    const int wr = wid >> 1, wc = wid & 1;
    const int g = lane >> 2, tg = lane & 3;

    for (int j = tid; j < 2048; j += 256) {
        int n = j >> 4, kc = (j & 15) * 8;
        *(uint4*)(Bh + n * LDA + kc) = *(const uint4*)(Whi + n * D + kc);
    }

    const int rowBase = blockIdx.x * 64;
    // 64 rows x 32 float4 = 2048 float4 / 256 thr = 8 each, 2 batches of 4
#pragma unroll
    for (int batch = 0; batch < 2; batch++) {
        float4 vv[4];
        float ss[4];
        int rr[4], kk[4];
#pragma unroll
        for (int u = 0; u < 4; u++) {
            int j = tid + (batch * 4 + u) * 256;
            rr[u] = j >> 5;
            kk[u] = (j & 31) * 4;
            int gr = rowBase + rr[u];
            if (gr < nrows) {
                vv[u] = *(const float4*)(A + (size_t)gr * D + kk[u]);
                ss[u] = rsqrtf((float)max(outc[gr], 1));
            } else {
                vv[u] = make_float4(0.f, 0.f, 0.f, 0.f);
                ss[u] = 0.0f;
            }
        }
#pragma unroll
        for (int u = 0; u < 4; u++) {
            __half2 o[2];
            o[0] = __floats2half2_rn(vv[u].x * ss[u], vv[u].y * ss[u]);
            o[1] = __floats2half2_rn(vv[u].z * ss[u], vv[u].w * ss[u]);
            *(uint2*)(As + rr[u] * LDA + kk[u]) = *(uint2*)o;
        }
    }
    __syncthreads();
    mma_phase64(As, Bh, Cm, rowBase, nrows, wr, wc, g, tg);
}

// ---------------- layer-2 GEMM: 64-row tile, fp8 A, fp8 out --------------------
__global__ __launch_bounds__(256, 4)
void k_gemm_tc8(const unsigned char* __restrict__ A,
                const __half* __restrict__ Whi,
                unsigned char* __restrict__ Cm, int nrows) {
    extern __shared__ __half sm[];
    __half* As = sm;
    __half* Bh = sm + 64 * LDA;

    const int tid = threadIdx.x;
    const int wid = tid >> 5, lane = tid & 31;
    const int wr = wid >> 1, wc = wid & 1;
    const int g = lane >> 2, tg = lane & 3;

    for (int j = tid; j < 2048; j += 256) {
        int n = j >> 4, kc = (j & 15) * 8;
        *(uint4*)(Bh + n * LDA + kc) = *(const uint4*)(Whi + n * D + kc);
    }

    const int rowBase = blockIdx.x * 64;
    // 64 rows x 16 uint2 = 1024 / 256 thr = 4 each, one batch
    {
        uint2 raw[4];
        int rr[4], kk[4];
#pragma unroll
        for (int u = 0; u < 4; u++) {
            int j = tid + u * 256;
            rr[u] = j >> 4;
            kk[u] = (j & 15) * 8;
            int gr = rowBase + rr[u];
            raw[u] = (gr < nrows)
                     ? *(const uint2*)(A + (size_t)gr * D + kk[u])
                     : make_uint2(0u, 0u);
        }
#pragma unroll
        for (int u = 0; u < 4; u++) {
            __half2 h[4];
            h[0] = fp8x2_to_h2(raw[u].x & 0xffffu);
            h[1] = fp8x2_to_h2(raw[u].x >> 16);
            h[2] = fp8x2_to_h2(raw[u].y & 0xffffu);
            h[3] = fp8x2_to_h2(raw[u].y >> 16);
            *(uint4*)(As + rr[u] * LDA + kk[u]) = *(uint4*)h;
        }
    }
    __syncthreads();
    mma_phase64(As, Bh, Cm, rowBase, nrows, wr, wc, g, tg);
}

// ---------------- gather accumulate helper --------------------------------------
__device__ __forceinline__ void acc_fp8x4(float4& acc, unsigned r) {
    float2 lo = unpack_fp8x2(r & 0xffffu);
    float2 hi = unpack_fp8x2(r >> 16);
    acc.x += lo.x; acc.y += lo.y; acc.z += hi.x; acc.w += hi.y;
}

// ---------------- gather + fused epilogue (+ optional fused pooling) ----------
template <int SCALE_OQ, int DO_POOL>
__global__ __launch_bounds__(256)
void k_gather(const int* __restrict__ csr, const int* __restrict__ rowp,
              const unsigned char* __restrict__ A, const float* __restrict__ isq,
              const float* __restrict__ b, const int* __restrict__ outc,
              unsigned char* __restrict__ out, int n, const int* __restrict__ n2g) {
    __shared__ float sacc[DO_POOL ? G * D : 1];
    if (DO_POOL) {
        for (int j = threadIdx.x; j < G * D; j += 256) sacc[j] = 0.0f;
        __syncthreads();
    }

    int w = (blockIdx.x * blockDim.x + threadIdx.x) >> 5;
    int lane = threadIdx.x & 31;
    int col = lane * 4;
    const unsigned FULL = 0xffffffffu;

    if (w < n) {
        int s0 = rowp[w], s1 = rowp[w + 1];
        float4 acc = make_float4(0.f, 0.f, 0.f, 0.f);

        for (int base = s0; base < s1; base += 32) {
            int cnt = min(32, s1 - base);
            int myidx = (lane < cnt) ? csr[base + lane] : 0;
            int t = 0;
            for (; t + 8 <= cnt; t += 8) {
                unsigned r[8];
#pragma unroll
                for (int u = 0; u < 8; u++) {
                    int s = __shfl_sync(FULL, myidx, t + u);
                    r[u] = *(const unsigned*)(A + (size_t)s * D + col);
                }
#pragma unroll
                for (int u = 0; u < 8; u++) acc_fp8x4(acc, r[u]);
            }
            for (; t < cnt; t++) {
                int s = __shfl_sync(FULL, myidx, t);
                acc_fp8x4(acc, *(const unsigned*)(A + (size_t)s * D + col));
            }
        }

        float sc = isq[w];
        float post = SCALE_OQ ? rsqrtf((float)max(outc[w], 1)) : 1.0f;
        float4 bb = *(const float4*)(b + col);
        float q0 = fmaxf(fmaf(acc.x, sc, bb.x), 0.0f) * post;
        float q1 = fmaxf(fmaf(acc.y, sc, bb.y), 0.0f) * post;
        float q2 = fmaxf(fmaf(acc.z, sc, bb.z), 0.0f) * post;
        float q3 = fmaxf(fmaf(acc.w, sc, bb.w), 0.0f) * post;

        if (!DO_POOL) {
            unsigned o = (unsigned)pack_fp8x2(q0, q1) |
                         ((unsigned)pack_fp8x2(q2, q3) << 16);
            *(unsigned*)(out + (size_t)w * D + col) = o;
        } else {
            int gidx = n2g[w] * D + col;
            atomicAdd(&sacc[gidx + 0], q0);
            atomicAdd(&sacc[gidx + 1], q1);
            atomicAdd(&sacc[gidx + 2], q2);
            atomicAdd(&sacc[gidx + 3], q3);
        }
    }

    if (DO_POOL) {
        __syncthreads();
        for (int j = threadIdx.x; j < G * D; j += 256) {
            float v = sacc[j];
            if (v != 0.0f) atomicAdd(&g_sums[j], v);
        }
    }
}

// ---------------- final: counts via binary search, mean -> linear -> softmax --
__global__ __launch_bounds__(128)
void k_final(const float* __restrict__ Wl, const float* __restrict__ bl,
             const int* __restrict__ n2g, int n, float* __restrict__ out) {
    __shared__ float hg[G * D];
    __shared__ float logits[G * C];
    __shared__ float scnt[G];
    int tid = threadIdx.x;
    if (tid < G) {
        int lo = 0, hi = n;
        while (lo < hi) { int m = (lo + hi) >> 1; if (n2g[m] < tid) lo = m + 1; else hi = m; }
        int lo2 = lo, hi2 = n;
        while (lo2 < hi2) { int m = (lo2 + hi2) >> 1; if (n2g[m] < tid + 1) lo2 = m + 1; else hi2 = m; }
        scnt[tid] = fmaxf((float)(lo2 - lo), 1.0f);
    }
    __syncthreads();
#pragma unroll
    for (int g = 0; g < G; g++)
        hg[g * D + tid] = g_sums[g * D + tid] / scnt[g];
    __syncthreads();
    if (tid < G * C) {
        int g = tid / C, c = tid % C;
        float acc = bl[c];
        for (int k = 0; k < D; k++) acc = fmaf(hg[g * D + k], Wl[k * C + c], acc);
        logits[tid] = acc;
    }
    __syncthreads();
    if (tid < G) {
        float m = -1e30f;
        for (int c = 0; c < C; c++) m = fmaxf(m, logits[tid * C + c]);
        float s = 0.0f;
        float e[C];
        for (int c = 0; c < C; c++) { e[c] = expf(logits[tid * C + c] - m); s += e[c]; }
        float inv = 1.0f / s;
        for (int c = 0; c < C; c++) out[tid * C + c] = e[c] * inv;
    }
}

// ---------------- launch --------------------------------------------------------
extern "C" void kernel_launch(void* const* d_in, const int* in_sizes, int n_in,
                              void* d_out, int out_size) {
    const float* x   = (const float*)d_in[0];
    const int*   ei  = (const int*)d_in[1];
    const int*   n2g = (const int*)d_in[2];
    const float* W1  = (const float*)d_in[3];
    const float* b1  = (const float*)d_in[4];
    const float* W2  = (const float*)d_in[5];
    const float* b2  = (const float*)d_in[6];
    const float* Wl  = (const float*)d_in[7];
    const float* bl  = (const float*)d_in[8];
    float* out = (float*)d_out;

    const int N = in_sizes[2];
    const int E = in_sizes[1] / 2;

    float* inq  = nullptr; cudaGetSymbolAddress((void**)&inq,  g_in_isqrt);
    unsigned char* hA = nullptr; cudaGetSymbolAddress((void**)&hA, g_h8A);
    unsigned char* hB = nullptr; cudaGetSymbolAddress((void**)&hB, g_h8B);
    __half* w1h = nullptr; cudaGetSymbolAddress((void**)&w1h, g_W1h);
    __half* w2h = nullptr; cudaGetSymbolAddress((void**)&w2h, g_W2h);
    float* sums = nullptr; cudaGetSymbolAddress((void**)&sums, g_sums);
    int* outc = nullptr; cudaGetSymbolAddress((void**)&outc, g_outcnt);
    int* inc  = nullptr; cudaGetSymbolAddress((void**)&inc,  g_incnt);
    int* rowp = nullptr; cudaGetSymbolAddress((void**)&rowp, g_rowptr);
    int* cur  = nullptr; cudaGetSymbolAddress((void**)&cur,  g_cursor);
    int* csr  = nullptr; cudaGetSymbolAddress((void**)&csr,  g_csr);
    int* bsum = nullptr; cudaGetSymbolAddress((void**)&bsum, g_bsums);

    const int nb = (N + 255) / 256;
    const int ntiles64 = (N + 63) / 64;
    const int gatherBlocks = (N * 32 + 255) / 256;
    const int smemGemm = (64 + 128) * LDA * (int)sizeof(__half);   // 52224

    static cudaStream_t s1;
    static cudaEvent_t ev_fork, ev_csr;
    static int s_init = 0;
    if (!s_init) {
        cudaFuncSetAttribute(k_gemm_tc,
                             cudaFuncAttributeMaxDynamicSharedMemorySize, smemGemm);
        cudaFuncSetAttribute(k_gemm_tc8,
                             cudaFuncAttributeMaxDynamicSharedMemorySize, smemGemm);
        cudaStreamCreateWithFlags(&s1, cudaStreamNonBlocking);
        cudaEventCreateWithFlags(&ev_fork, cudaEventDisableTiming);
        cudaEventCreateWithFlags(&ev_csr, cudaEventDisableTiming);
        s_init = 1;
    }

    // fork s1 at t=0 (the two chains share no data until gather1)
    cudaEventRecord(ev_fork, 0);
    cudaStreamWaitEvent(s1, ev_fork, 0);

    // main chain: prep(1) -> degout(2) -> gemm1(4: profiled slot)
    k_prep<<<nb, 256>>>(outc, N, W1, W2, w1h, w2h);
    k_degout<<<(E + 255) / 256, 256>>>(ei, E, outc);
    k_zero2<<<nb, 256, 0, s1>>>(inc, N, sums);                       // (3)
    k_gemm_tc<<<ntiles64, 256, smemGemm>>>(x, outc, w1h, hA, N);     // (4)

    // s1 chain: degin -> scan1 -> scan3 -> fill
    k_degin<<<(E + 255) / 256, 256, 0, s1>>>(ei, E, inc);
    k_scan1<<<nb, 256, 0, s1>>>(inc, N, bsum);
    k_scan3<<<nb, 256, 0, s1>>>(inc, N, nb, E, bsum, rowp, cur, inq);
    k_fill<<<(E + 255) / 256, 256, 0, s1>>>(ei, E, cur, csr);

    cudaEventRecord(ev_csr, s1);
    cudaStreamWaitEvent(0, ev_csr, 0);

    // gather1 (folds oq), gemm2, gather2 + fused pool
    k_gather<1, 0><<<gatherBlocks, 256>>>(csr, rowp, hA, inq, b1, outc, hB, N, n2g);
    k_gemm_tc8<<<ntiles64, 256, smemGemm>>>(hB, w2h, hA, N);
    k_gather<0, 1><<<gatherBlocks, 256>>>(csr, rowp, hA, inq, b2, outc, hB, N, n2g);

    // head
    k_final<<<1, 128>>>(Wl, bl, n2g, N, out);
}